// round 15
// baseline (speedup 1.0000x reference)
#include <cuda_runtime.h>
#include <cuda_bf16.h>
#include <cstdint>

// Problem constants
#define NB 2
#define NL 256
#define NE 512
#define NH 8
#define ND 64   // head dim
// scale = 1/sqrt(64) = 0.125

// ---------------- device scratch (no allocations allowed) ----------------
__device__ float g_qp[NB*NL*NE];
__device__ float g_kp[NB*NL*NE];
__device__ float g_vp[NB*NL*NE];
__device__ float g_wk2[NB*NL*NH*NE];     // [b,k,h,g], pre-scaled by 1/8
__device__ float g_bias2[NB*NL*NH];      // pre-scaled by 1/8
__device__ float g_S1[NB*NH*NL*NL];      // [b,h,q,k], pre-scaled by 1/8
__device__ float g_S[NB*NL*NL*NH];       // rel logit part, [b,q,k,h]
__device__ float g_P[NB*NH*NL*NL];       // probs, [b,h,q,k]
__device__ float g_attn[NB*NL*NE];       // [b,q, h*64+e]

// ---------------- packed f32x2 helpers ----------------
__device__ __forceinline__ unsigned long long f2pack(float lo, float hi) {
    unsigned long long r;
    asm("mov.b64 %0, {%1, %2};" : "=l"(r) : "f"(lo), "f"(hi));
    return r;
}
__device__ __forceinline__ void f2unpack(float& lo, float& hi, unsigned long long v) {
    asm("mov.b64 {%0, %1}, %2;" : "=f"(lo), "=f"(hi) : "l"(v));
}
__device__ __forceinline__ void fma2(unsigned long long& d,
                                     unsigned long long a, unsigned long long b) {
    asm("fma.rn.f32x2 %0, %1, %2, %0;" : "+l"(d) : "l"(a), "l"(b));
}
__device__ __forceinline__ unsigned long long add2(unsigned long long a,
                                                   unsigned long long b) {
    unsigned long long r;
    asm("add.rn.f32x2 %0, %1, %2;" : "=l"(r) : "l"(a), "l"(b));
    return r;
}

// ---------------- cp.async helpers (base PTX, sm_80+) ----------------
#define CP_ASYNC_CG(dst_u32, src_ptr) \
    asm volatile("cp.async.cg.shared.global [%0], [%1], 16;" \
        :: "r"(dst_u32), "l"(src_ptr) : "memory")
#define CP_ASYNC_COMMIT() \
    asm volatile("cp.async.commit_group;" ::: "memory")
#define CP_ASYNC_WAIT(N) \
    asm volatile("cp.async.wait_group %0;" :: "n"(N) : "memory")

// ---------------- warp-mma helpers (base PTX, sm_80+: valid on sm_103) ----------------
__device__ __forceinline__ uint32_t smem_addr_u32(const void* p) {
    return (uint32_t)__cvta_generic_to_shared(p);
}
__device__ __forceinline__ void ldsm4(uint32_t* r, uint32_t a) {
    asm volatile("ldmatrix.sync.aligned.m8n8.x4.shared.b16 {%0,%1,%2,%3}, [%4];"
        : "=r"(r[0]), "=r"(r[1]), "=r"(r[2]), "=r"(r[3]) : "r"(a));
}
__device__ __forceinline__ void ldsm4t(uint32_t* r, uint32_t a) {
    asm volatile("ldmatrix.sync.aligned.m8n8.x4.trans.shared.b16 {%0,%1,%2,%3}, [%4];"
        : "=r"(r[0]), "=r"(r[1]), "=r"(r[2]), "=r"(r[3]) : "r"(a));
}
__device__ __forceinline__ void mma_bf16(float* c, const uint32_t* a, const uint32_t* b) {
    asm volatile("mma.sync.aligned.m16n8k16.row.col.f32.bf16.bf16.f32 "
        "{%0,%1,%2,%3}, {%4,%5,%6,%7}, {%8,%9}, {%0,%1,%2,%3};"
        : "+f"(c[0]), "+f"(c[1]), "+f"(c[2]), "+f"(c[3])
        : "r"(a[0]), "r"(a[1]), "r"(a[2]), "r"(a[3]), "r"(b[0]), "r"(b[1]));
}

// ---------------- GEMM v5b: bf16-split tensor-core GEMM with LDG prefetch ----------------
// C[m,n] = alpha * sum_k A[m,k]*B[k,n]   (TRANS_B: B stored [n,k])  (+bias[n])
// Block tile 128(m) x 64(n), 256 threads = 8 warps (4m x 2n), warp tile 32x32.
template<bool TRANS_B>
__device__ __forceinline__ void gemm_mma(
    const float* __restrict__ A, int lda,
    const float* __restrict__ B, int ldb,
    float* __restrict__ C, int ldc,
    int K, float alpha, const float* __restrict__ bias)
{
    constexpr int SAS = 40;                  // sA row stride (elems): 80B, 16B-aligned
    constexpr int SBR = TRANS_B ? 64 : 32;   // sB rows
    constexpr int SBS = TRANS_B ? 40 : 72;   // sB row stride (80B / 144B)
    __shared__ __nv_bfloat16 sAh[128 * SAS], sAl[128 * SAS];
    __shared__ __nv_bfloat16 sBh[SBR * SBS], sBl[SBR * SBS];

    const int tid = threadIdx.x;
    const int lane = tid & 31;
    const int wid = tid >> 5;
    const int wm = wid & 3;                  // warp m index (0..3)
    const int wn = wid >> 2;                 // warp n index (0..1)
    const int bm = blockIdx.y * 128;
    const int bn = blockIdx.x * 64;

    const uint32_t sAh_b = smem_addr_u32(sAh);
    const uint32_t sAl_b = smem_addr_u32(sAl);
    const uint32_t sBh_b = smem_addr_u32(sBh);
    const uint32_t sBl_b = smem_addr_u32(sBl);

    const int aRowL = wm * 32 + (lane & 15);          // + mt*16
    const int aColL = (lane >> 4) * 8;                // + kk
    const int bRowL = TRANS_B ? (wn * 32 + (lane & 7) + (lane >> 4) * 8)
                              : ((lane & 7) + ((lane >> 3) & 1) * 8);
    const int bColL = TRANS_B ? (((lane >> 3) & 1) * 8)
                              : (wn * 32 + (lane >> 4) * 8);

    // staging indices
    const int aSRow = tid >> 3, aSC4 = (tid & 7) * 4;
    const int bSRowN = tid >> 4, bSC4N = (tid & 15) * 4;
    const int bSRowT = tid >> 3, bSC4T = (tid & 7) * 4;

    float4 aR[4], bR[2];
    auto ldg = [&](int k0) {
#pragma unroll
        for (int i = 0; i < 4; i++)
            aR[i] = *reinterpret_cast<const float4*>(
                A + (size_t)(bm + aSRow + i * 32) * lda + k0 + aSC4);
#pragma unroll
        for (int i = 0; i < 2; i++) {
            if (!TRANS_B)
                bR[i] = *reinterpret_cast<const float4*>(
                    B + (size_t)(k0 + bSRowN + i * 16) * ldb + bn + bSC4N);
            else
                bR[i] = *reinterpret_cast<const float4*>(
                    B + (size_t)(bn + bSRowT + i * 32) * ldb + k0 + bSC4T);
        }
    };
    auto split_store = [&](__nv_bfloat16* hB, __nv_bfloat16* lB, int idx, float4 v) {
        __nv_bfloat162 h01 = __floats2bfloat162_rn(v.x, v.y);
        __nv_bfloat162 h23 = __floats2bfloat162_rn(v.z, v.w);
        float2 f01 = __bfloat1622float2(h01);
        float2 f23 = __bfloat1622float2(h23);
        __nv_bfloat162 l01 = __floats2bfloat162_rn(v.x - f01.x, v.y - f01.y);
        __nv_bfloat162 l23 = __floats2bfloat162_rn(v.z - f23.x, v.w - f23.y);
        *reinterpret_cast<__nv_bfloat162*>(&hB[idx])     = h01;
        *reinterpret_cast<__nv_bfloat162*>(&hB[idx + 2]) = h23;
        *reinterpret_cast<__nv_bfloat162*>(&lB[idx])     = l01;
        *reinterpret_cast<__nv_bfloat162*>(&lB[idx + 2]) = l23;
    };
    auto sts = [&]() {
#pragma unroll
        for (int i = 0; i < 4; i++)
            split_store(sAh, sAl, (aSRow + i * 32) * SAS + aSC4, aR[i]);
#pragma unroll
        for (int i = 0; i < 2; i++) {
            int idx = (!TRANS_B) ? ((bSRowN + i * 16) * SBS + bSC4N)
                                 : ((bSRowT + i * 32) * SBS + bSC4T);
            split_store(sBh, sBl, idx, bR[i]);
        }
    };

    float acc[2][4][4];
#pragma unroll
    for (int mt = 0; mt < 2; mt++)
#pragma unroll
        for (int nt = 0; nt < 4; nt++)
#pragma unroll
            for (int j = 0; j < 4; j++) acc[mt][nt][j] = 0.f;

    const int nchunk = K / 32;
    ldg(0);
    sts();
    __syncthreads();

    for (int c = 0; c < nchunk; ++c) {
        if (c + 1 < nchunk) ldg((c + 1) * 32);   // prefetch overlaps MMAs below

#pragma unroll
        for (int kk = 0; kk < 32; kk += 16) {
            uint32_t afr[2][4], bh[8], bl[8];
#pragma unroll
            for (int mt = 0; mt < 2; mt++) {
                uint32_t off = (uint32_t)(((aRowL + mt * 16) * SAS + aColL + kk) * 2);
                ldsm4(afr[mt], sAh_b + off);
            }
#pragma unroll
            for (int ntp = 0; ntp < 2; ntp++) {
                uint32_t off;
                if (!TRANS_B)
                    off = (uint32_t)(((bRowL + kk) * SBS + bColL + ntp * 16) * 2);
                else
                    off = (uint32_t)(((bRowL + ntp * 16) * SBS + bColL + kk) * 2);
                if (!TRANS_B) {
                    ldsm4t(&bh[ntp * 4], sBh_b + off);
                    ldsm4t(&bl[ntp * 4], sBl_b + off);
                } else {
                    ldsm4(&bh[ntp * 4], sBh_b + off);
                    ldsm4(&bl[ntp * 4], sBl_b + off);
                }
            }
#pragma unroll
            for (int mt = 0; mt < 2; mt++)
#pragma unroll
                for (int nt = 0; nt < 4; nt++) {
                    const uint32_t* bp = &bh[(nt >> 1) * 4 + (nt & 1) * 2];
                    const uint32_t* lp = &bl[(nt >> 1) * 4 + (nt & 1) * 2];
                    mma_bf16(acc[mt][nt], afr[mt], bp);
                    mma_bf16(acc[mt][nt], afr[mt], lp);
                }
#pragma unroll
            for (int mt = 0; mt < 2; mt++) {
                uint32_t off = (uint32_t)(((aRowL + mt * 16) * SAS + aColL + kk) * 2);
                ldsm4(afr[mt], sAl_b + off);
            }
#pragma unroll
            for (int mt = 0; mt < 2; mt++)
#pragma unroll
                for (int nt = 0; nt < 4; nt++)
                    mma_bf16(acc[mt][nt], afr[mt], &bh[(nt >> 1) * 4 + (nt & 1) * 2]);
        }

        if (c + 1 < nchunk) {
            __syncthreads();
            sts();
            __syncthreads();
        }
    }

    // ---- epilogue ----
    const int r0 = bm + wm * 32 + (lane >> 2);
    const int c0 = bn + wn * 32 + (lane & 3) * 2;
#pragma unroll
    for (int mt = 0; mt < 2; mt++)
#pragma unroll
        for (int nt = 0; nt < 4; nt++) {
            const int row = r0 + mt * 16;
            const int col = c0 + nt * 8;
            float2 v0, v1;
            v0.x = acc[mt][nt][0] * alpha; v0.y = acc[mt][nt][1] * alpha;
            v1.x = acc[mt][nt][2] * alpha; v1.y = acc[mt][nt][3] * alpha;
            if (bias) {
                v0.x += bias[col]; v0.y += bias[col + 1];
                v1.x += bias[col]; v1.y += bias[col + 1];
            }
            *reinterpret_cast<float2*>(C + (size_t)row * ldc + col) = v0;
            *reinterpret_cast<float2*>(C + (size_t)(row + 8) * ldc + col) = v1;
        }
}

// ---------------- K1: projections qp = query@Wq, kp = key@Wk, vp = value@Wq ----------------
__global__ void __launch_bounds__(256) k_proj(
    const float* __restrict__ q, const float* __restrict__ k,
    const float* __restrict__ v,
    const float* __restrict__ Wq, const float* __restrict__ Wk)
{
    int z = blockIdx.z;
    const float* A = (z == 0) ? q : (z == 1) ? k : v;
    const float* W = (z == 1) ? Wk : Wq;   // value uses Wq (bug preserved from source)
    float* C = (z == 0) ? g_qp : (z == 1) ? g_kp : g_vp;
    gemm_mma<false>(A, NE, W, NE, C, NE, NE, 1.0f, nullptr);
}

// ---------------- K2 (merged): wk2 (z<8), S1 (z in 8..23) ----------------
__global__ void __launch_bounds__(256) k_mid(const float* __restrict__ Wr)
{
    const int z = blockIdx.z;
    if (z < 8) {
        // Wk2[b,k,h,:] = (1/8) * kp_head(b,k,h,:) @ Wr[h*64:(h+1)*64, :]
        const int h = z;
        gemm_mma<false>(g_kp + h * ND, NE,
                        Wr + (size_t)h * ND * NE, NE,
                        g_wk2 + (size_t)h * NE, NH * NE,
                        ND, 0.125f, nullptr);
    } else {
        // S1[b,h,q,k] = (1/8) * qp_h @ kp_h^T
        if (blockIdx.x >= 4 || blockIdx.y >= 2) return;
        const int zz = z - 8;            // b*NH + h
        const int b = zz >> 3, h = zz & 7;
        gemm_mma<true>(g_qp + (size_t)b * NL * NE + h * ND, NE,
                       g_kp + (size_t)b * NL * NE + h * ND, NE,
                       g_S1 + (size_t)zz * NL * NL, NL,
                       ND, 0.125f, nullptr);
    }
}

// ---------------- K3: bias2[b,k,h] = (1/8) * dot(br_head, kp_head) ----------------
__global__ void k_bias2(const float* __restrict__ br)
{
    int idx = blockIdx.x * blockDim.x + threadIdx.x;  // NB*NL*NH = 4096
    if (idx >= NB * NL * NH) return;
    int h = idx & (NH - 1);
    int row = idx >> 3;
    float s = 0.f;
#pragma unroll 8
    for (int e = 0; e < ND; e++)
        s += br[h * ND + e] * g_kp[(size_t)row * NE + h * ND + e];
    g_bias2[idx] = s * 0.125f;
}

// ---------------- K4: relation stream v4 — rolling per-warp cp.async ring ----------------
// Block = (kpos, b, qhalf): 128 q-rows, 512 threads = 16 warps.
// Warp w owns rows {o*64 + w*4 .. +3} for o in {0,1}; 8 chunks/warp
// (chunk c: row group o = c>>2, g-stage s = c&3; 4 rows x 128 g = 2KB).
// Depth-6 per-warp ring, one commit group per chunk, empty commits pad the
// accounting -> fetches stay in flight for the whole block. No block syncs in
// the loop. S1 is NOT added here (moved to softmax, coalesced there).
// smem: wk2 16KB @0, bias2 @16384, ring @16416: [16 warps][6][2048B] = 192KB.
#define REL_D 6
#define REL_SMEM (16416 + 16 * REL_D * 2048)
__global__ void __launch_bounds__(512) k_rel(const float* __restrict__ relation)
{
    extern __shared__ char dsm[];
    float* wk  = reinterpret_cast<float*>(dsm);           // [8][512]
    float* b2s = reinterpret_cast<float*>(dsm + 16384);   // [8]
    char* ring = dsm + 16416;                             // [16][REL_D][2048]

    const int kpos = blockIdx.x;
    const int b = blockIdx.y;
    const int qbase = blockIdx.z * 128;
    const int tid = threadIdx.x;
    const int warp = tid >> 5;     // 0..15
    const int lane = tid & 31;

    const uint32_t wbase = smem_addr_u32(ring) + warp * (REL_D * 2048);
    const float* relw = relation +
        ((size_t)(b * NL + qbase + warp * 4) * NL + kpos) * NE + lane * 4;

    auto issue_chunk = [&](int c) {
        const int o = c >> 2, s = c & 3;
        const int slot = c % REL_D;
        const uint32_t dst = wbase + slot * 2048 + lane * 16;
        const float* src = relw + (size_t)(o * 64) * (NL * NE) + s * 128;
#pragma unroll
        for (int j = 0; j < 4; j++)
            CP_ASYNC_CG(dst + j * 512, src + (size_t)j * (NL * NE));
        CP_ASYNC_COMMIT();
    };

    // prologue: fill the ring
#pragma unroll
    for (int c = 0; c < REL_D; c++) issue_chunk(c);

    // cooperative wk2 + bias2 load (overlaps cp.async fetch)
    {
        const float4* src = reinterpret_cast<const float4*>(
            g_wk2 + (size_t)(b * NL + kpos) * NH * NE);
        float4* dst4 = reinterpret_cast<float4*>(wk);
        for (int i = tid; i < NH * NE / 4; i += 512) dst4[i] = src[i];
        if (tid < NH) b2s[tid] = g_bias2[(size_t)(b * NL + kpos) * NH + tid];
    }
    __syncthreads();   // wk visible to all warps

    unsigned long long acc[32];    // acc[j*8+h], (even-g, odd-g) packed
#pragma unroll
    for (int i = 0; i < 32; i++) acc[i] = 0ull;

#pragma unroll
    for (int c = 0; c < 8; c++) {
        CP_ASYNC_WAIT(REL_D - 1);   // invariant: issued = c + REL_D -> chunk c done
        __syncwarp();

        const int o = c >> 2, s = c & 3;
        const float* stf = reinterpret_cast<const float*>(
            ring + warp * (REL_D * 2048) + (c % REL_D) * 2048);
        ulonglong2 r[4];
#pragma unroll
        for (int j = 0; j < 4; j++)
            r[j] = *reinterpret_cast<const ulonglong2*>(stf + j * 128 + lane * 4);

        const int gofs = s * 128 + lane * 4;
#pragma unroll
        for (int h = 0; h < 8; h++) {
            ulonglong2 w = *reinterpret_cast<const ulonglong2*>(&wk[h * NE + gofs]);
#pragma unroll
            for (int j = 0; j < 4; j++) {
                fma2(acc[j * 8 + h], r[j].x, w.x);
                fma2(acc[j * 8 + h], r[j].y, w.y);
            }
        }

        // keep the group accounting rolling (real chunk or empty commit)
        if (c + REL_D < 8) issue_chunk(c + REL_D);
        else CP_ASYNC_COMMIT();

        if ((c & 3) == 3) {
            // u64 butterfly transpose-reduce for row group o, then store
#pragma unroll
            for (int off = 16; off > 0; off >>= 1) {
                bool hi = (lane & off) != 0;
#pragma unroll
                for (int i = 0; i < 16; i++) {
                    if (i < off) {
                        unsigned long long send = hi ? acc[i] : acc[i + off];
                        unsigned long long recv = __shfl_xor_sync(0xffffffffu, send, off);
                        unsigned long long keep = hi ? acc[i + off] : acc[i];
                        acc[i] = add2(keep, recv);
                    }
                }
            }
            float lo, hf;
            f2unpack(lo, hf, acc[0]);
            float fin = lo + hf;
            const int j = lane >> 3;
            const int h = lane & 7;
            const int q = qbase + o * 64 + warp * 4 + j;
            g_S[(((size_t)b * NL + q) * NL + kpos) * NH + h] = fin + b2s[h];
#pragma unroll
            for (int i = 0; i < 32; i++) acc[i] = 0ull;
        }
    }
}

// ---------------- K5: softmax over k (adds S1 here, coalesced) + write probs ----------------
__global__ void __launch_bounds__(256) k_softmax(float* __restrict__ a_out, int write_a)
{
    const int q = blockIdx.x;
    const int b = blockIdx.y;
    const int tid = threadIdx.x;
    const int warp = tid >> 5;   // = head
    const int lane = tid & 31;

    __shared__ float Ss[NL][NH + 1];   // padded

    const float* Srow = g_S + (size_t)(b * NL + q) * NL * NH;
    for (int i = tid; i < NL * NH / 4; i += 256) {
        float4 v = reinterpret_cast<const float4*>(Srow)[i];
        int idx = i * 4;
        int kk = idx >> 3, h0 = idx & 7;
        Ss[kk][h0] = v.x; Ss[kk][h0 + 1] = v.y;
        Ss[kk][h0 + 2] = v.z; Ss[kk][h0 + 3] = v.w;
    }
    __syncthreads();

    const int h = warp;
    // S1[b,h,q,:] contiguous in k -> coalesced within the warp
    const float* S1h = g_S1 + (((size_t)b * NH + h) * NL + q) * NL;
    float x[8];
#pragma unroll
    for (int i = 0; i < 8; i++) x[i] = Ss[lane + 32 * i][h] + S1h[lane + 32 * i];

    float m = x[0];
#pragma unroll
    for (int i = 1; i < 8; i++) m = fmaxf(m, x[i]);
#pragma unroll
    for (int off = 16; off > 0; off >>= 1)
        m = fmaxf(m, __shfl_xor_sync(0xffffffffu, m, off));

    float e[8], s = 0.f;
#pragma unroll
    for (int i = 0; i < 8; i++) { e[i] = __expf(x[i] - m); s += e[i]; }
#pragma unroll
    for (int off = 16; off > 0; off >>= 1)
        s += __shfl_xor_sync(0xffffffffu, s, off);
    float inv = 1.0f / s;

    float* Prow = g_P + (((size_t)b * NH + h) * NL + q) * NL;
#pragma unroll
    for (int i = 0; i < 8; i++) {
        float p = e[i] * inv;
        Prow[lane + 32 * i] = p;
        Ss[lane + 32 * i][h] = p;    // own column only
    }
    __syncthreads();

    if (write_a) {
        float* arow = a_out + (size_t)(b * NL + q) * NL * NH;
        int t = tid;
        float4 v0 = make_float4(Ss[t][0], Ss[t][1], Ss[t][2], Ss[t][3]);
        float4 v1 = make_float4(Ss[t][4], Ss[t][5], Ss[t][6], Ss[t][7]);
        reinterpret_cast<float4*>(arow + t * 8)[0] = v0;
        reinterpret_cast<float4*>(arow + t * 8)[1] = v1;
    }
}

// ---------------- K6: attn = P @ vp per (b,h) ----------------
__global__ void __launch_bounds__(256) k_attn()
{
    int z = blockIdx.z;           // b*NH + h
    int b = z >> 3, h = z & 7;
    const float* A = g_P + (size_t)z * NL * NL;              // L x L
    const float* Bw = g_vp + (size_t)b * NL * NE + h * ND;   // L x 64, ldb=NE
    float* C = g_attn + (size_t)b * NL * NE + h * ND;        // ldc=NE
    gemm_mma<false>(A, NL, Bw, NE, C, NE, NL, 1.0f, nullptr);
}

// ---------------- K7: out = attn @ Wo^T + bo ----------------
__global__ void __launch_bounds__(256) k_out(
    const float* __restrict__ Wo, const float* __restrict__ bo,
    float* __restrict__ out)
{
    gemm_mma<true>(g_attn, NE, Wo, NE, out, NE, NE, 1.0f, bo);
}

// ---------------- launch ----------------
extern "C" void kernel_launch(void* const* d_in, const int* in_sizes, int n_in,
                              void* d_out, int out_size)
{
    const float* query    = (const float*)d_in[0];
    const float* key      = (const float*)d_in[1];
    const float* value    = (const float*)d_in[2];
    const float* relation = (const float*)d_in[3];
    const float* Wq       = (const float*)d_in[4];
    const float* Wk       = (const float*)d_in[5];
    // d_in[6] = Wv — unused (source bug: value projected with Wq)
    const float* Wr       = (const float*)d_in[7];
    const float* br       = (const float*)d_in[8];
    const float* Wo       = (const float*)d_in[9];
    const float* bo       = (const float*)d_in[10];

    float* out = (float*)d_out;
    const int out_elems = NB * NL * NE;            // 262144
    const int a_elems   = NB * NL * NL * NH;       // 1048576
    int write_a = (out_size >= out_elems + a_elems) ? 1 : 0;
    float* a_out = out + out_elems;

    // raise dynamic-smem limit for k_rel (capture-safe: not a stream op)
    cudaFuncSetAttribute((const void*)k_rel,
                         cudaFuncAttributeMaxDynamicSharedMemorySize, REL_SMEM);

    dim3 blk(256);
    k_proj   <<<dim3(8, 4, 3),   blk>>>(query, key, value, Wq, Wk);
    k_mid    <<<dim3(8, 4, 24),  blk>>>(Wr);
    k_bias2  <<<16, 256>>>(br);
    k_rel    <<<dim3(NL, NB, 2), dim3(512), REL_SMEM>>>(relation);  // idx 3 -> profiled
    k_softmax<<<dim3(NL, NB),    blk>>>(a_out, write_a);
    k_attn   <<<dim3(1, 2, 16),  blk>>>();
    k_out    <<<dim3(8, 4, 1),   blk>>>(Wo, bo, out);
}

// round 16
// speedup vs baseline: 1.1415x; 1.1415x over previous
#include <cuda_runtime.h>
#include <cuda_bf16.h>
#include <cstdint>

// Problem constants
#define NB 2
#define NL 256
#define NE 512
#define NH 8
#define ND 64   // head dim
// scale = 1/sqrt(64) = 0.125

// ---------------- device scratch (no allocations allowed) ----------------
__device__ float g_qp[NB*NL*NE];
__device__ float g_kp[NB*NL*NE];
__device__ float g_vp[NB*NL*NE];
__device__ float g_wk2[NB*NL*NH*NE];     // [b,k,h,g], pre-scaled by 1/8
__device__ float g_bias2[NB*NL*NH];      // pre-scaled by 1/8
__device__ float g_S1[NB*NH*NL*NL];      // [b,h,q,k], pre-scaled by 1/8
__device__ float g_S[NB*NL*NL*NH];       // rel logit part, [b,q,k,h]
__device__ float g_P[NB*NH*NL*NL];       // probs, [b,h,q,k]
__device__ float g_attn[NB*NL*NE];       // [b,q, h*64+e]

// ---------------- packed f32x2 helpers ----------------
__device__ __forceinline__ unsigned long long f2pack(float lo, float hi) {
    unsigned long long r;
    asm("mov.b64 %0, {%1, %2};" : "=l"(r) : "f"(lo), "f"(hi));
    return r;
}
__device__ __forceinline__ void f2unpack(float& lo, float& hi, unsigned long long v) {
    asm("mov.b64 {%0, %1}, %2;" : "=f"(lo), "=f"(hi) : "l"(v));
}
__device__ __forceinline__ void fma2(unsigned long long& d,
                                     unsigned long long a, unsigned long long b) {
    asm("fma.rn.f32x2 %0, %1, %2, %0;" : "+l"(d) : "l"(a), "l"(b));
}
__device__ __forceinline__ unsigned long long add2(unsigned long long a,
                                                   unsigned long long b) {
    unsigned long long r;
    asm("add.rn.f32x2 %0, %1, %2;" : "=l"(r) : "l"(a), "l"(b));
    return r;
}

// ---------------- cp.async helpers (base PTX, sm_80+) ----------------
#define CP_ASYNC_CG(dst_u32, src_ptr) \
    asm volatile("cp.async.cg.shared.global [%0], [%1], 16;" \
        :: "r"(dst_u32), "l"(src_ptr) : "memory")
#define CP_ASYNC_COMMIT() \
    asm volatile("cp.async.commit_group;" ::: "memory")
#define CP_ASYNC_WAIT(N) \
    asm volatile("cp.async.wait_group %0;" :: "n"(N) : "memory")

// ---------------- warp-mma helpers (base PTX, sm_80+: valid on sm_103) ----------------
__device__ __forceinline__ uint32_t smem_addr_u32(const void* p) {
    return (uint32_t)__cvta_generic_to_shared(p);
}
__device__ __forceinline__ void ldsm4(uint32_t* r, uint32_t a) {
    asm volatile("ldmatrix.sync.aligned.m8n8.x4.shared.b16 {%0,%1,%2,%3}, [%4];"
        : "=r"(r[0]), "=r"(r[1]), "=r"(r[2]), "=r"(r[3]) : "r"(a));
}
__device__ __forceinline__ void ldsm4t(uint32_t* r, uint32_t a) {
    asm volatile("ldmatrix.sync.aligned.m8n8.x4.trans.shared.b16 {%0,%1,%2,%3}, [%4];"
        : "=r"(r[0]), "=r"(r[1]), "=r"(r[2]), "=r"(r[3]) : "r"(a));
}
__device__ __forceinline__ void mma_bf16(float* c, const uint32_t* a, const uint32_t* b) {
    asm volatile("mma.sync.aligned.m16n8k16.row.col.f32.bf16.bf16.f32 "
        "{%0,%1,%2,%3}, {%4,%5,%6,%7}, {%8,%9}, {%0,%1,%2,%3};"
        : "+f"(c[0]), "+f"(c[1]), "+f"(c[2]), "+f"(c[3])
        : "r"(a[0]), "r"(a[1]), "r"(a[2]), "r"(a[3]), "r"(b[0]), "r"(b[1]));
}

// ---------------- GEMM v5b: bf16-split tensor-core GEMM with LDG prefetch ----------------
// C[m,n] = alpha * sum_k A[m,k]*B[k,n]   (TRANS_B: B stored [n,k])  (+bias[n])
// Block tile 128(m) x 64(n), 256 threads = 8 warps (4m x 2n), warp tile 32x32.
template<bool TRANS_B>
__device__ __forceinline__ void gemm_mma(
    const float* __restrict__ A, int lda,
    const float* __restrict__ B, int ldb,
    float* __restrict__ C, int ldc,
    int K, float alpha, const float* __restrict__ bias)
{
    constexpr int SAS = 40;                  // sA row stride (elems): 80B, 16B-aligned
    constexpr int SBR = TRANS_B ? 64 : 32;   // sB rows
    constexpr int SBS = TRANS_B ? 40 : 72;   // sB row stride (80B / 144B)
    __shared__ __nv_bfloat16 sAh[128 * SAS], sAl[128 * SAS];
    __shared__ __nv_bfloat16 sBh[SBR * SBS], sBl[SBR * SBS];

    const int tid = threadIdx.x;
    const int lane = tid & 31;
    const int wid = tid >> 5;
    const int wm = wid & 3;                  // warp m index (0..3)
    const int wn = wid >> 2;                 // warp n index (0..1)
    const int bm = blockIdx.y * 128;
    const int bn = blockIdx.x * 64;

    const uint32_t sAh_b = smem_addr_u32(sAh);
    const uint32_t sAl_b = smem_addr_u32(sAl);
    const uint32_t sBh_b = smem_addr_u32(sBh);
    const uint32_t sBl_b = smem_addr_u32(sBl);

    const int aRowL = wm * 32 + (lane & 15);          // + mt*16
    const int aColL = (lane >> 4) * 8;                // + kk
    const int bRowL = TRANS_B ? (wn * 32 + (lane & 7) + (lane >> 4) * 8)
                              : ((lane & 7) + ((lane >> 3) & 1) * 8);
    const int bColL = TRANS_B ? (((lane >> 3) & 1) * 8)
                              : (wn * 32 + (lane >> 4) * 8);

    // staging indices
    const int aSRow = tid >> 3, aSC4 = (tid & 7) * 4;
    const int bSRowN = tid >> 4, bSC4N = (tid & 15) * 4;
    const int bSRowT = tid >> 3, bSC4T = (tid & 7) * 4;

    float4 aR[4], bR[2];
    auto ldg = [&](int k0) {
#pragma unroll
        for (int i = 0; i < 4; i++)
            aR[i] = *reinterpret_cast<const float4*>(
                A + (size_t)(bm + aSRow + i * 32) * lda + k0 + aSC4);
#pragma unroll
        for (int i = 0; i < 2; i++) {
            if (!TRANS_B)
                bR[i] = *reinterpret_cast<const float4*>(
                    B + (size_t)(k0 + bSRowN + i * 16) * ldb + bn + bSC4N);
            else
                bR[i] = *reinterpret_cast<const float4*>(
                    B + (size_t)(bn + bSRowT + i * 32) * ldb + k0 + bSC4T);
        }
    };
    auto split_store = [&](__nv_bfloat16* hB, __nv_bfloat16* lB, int idx, float4 v) {
        __nv_bfloat162 h01 = __floats2bfloat162_rn(v.x, v.y);
        __nv_bfloat162 h23 = __floats2bfloat162_rn(v.z, v.w);
        float2 f01 = __bfloat1622float2(h01);
        float2 f23 = __bfloat1622float2(h23);
        __nv_bfloat162 l01 = __floats2bfloat162_rn(v.x - f01.x, v.y - f01.y);
        __nv_bfloat162 l23 = __floats2bfloat162_rn(v.z - f23.x, v.w - f23.y);
        *reinterpret_cast<__nv_bfloat162*>(&hB[idx])     = h01;
        *reinterpret_cast<__nv_bfloat162*>(&hB[idx + 2]) = h23;
        *reinterpret_cast<__nv_bfloat162*>(&lB[idx])     = l01;
        *reinterpret_cast<__nv_bfloat162*>(&lB[idx + 2]) = l23;
    };
    auto sts = [&]() {
#pragma unroll
        for (int i = 0; i < 4; i++)
            split_store(sAh, sAl, (aSRow + i * 32) * SAS + aSC4, aR[i]);
#pragma unroll
        for (int i = 0; i < 2; i++) {
            int idx = (!TRANS_B) ? ((bSRowN + i * 16) * SBS + bSC4N)
                                 : ((bSRowT + i * 32) * SBS + bSC4T);
            split_store(sBh, sBl, idx, bR[i]);
        }
    };

    float acc[2][4][4];
#pragma unroll
    for (int mt = 0; mt < 2; mt++)
#pragma unroll
        for (int nt = 0; nt < 4; nt++)
#pragma unroll
            for (int j = 0; j < 4; j++) acc[mt][nt][j] = 0.f;

    const int nchunk = K / 32;
    ldg(0);
    sts();
    __syncthreads();

    for (int c = 0; c < nchunk; ++c) {
        if (c + 1 < nchunk) ldg((c + 1) * 32);   // prefetch overlaps MMAs below

#pragma unroll
        for (int kk = 0; kk < 32; kk += 16) {
            uint32_t afr[2][4], bh[8], bl[8];
#pragma unroll
            for (int mt = 0; mt < 2; mt++) {
                uint32_t off = (uint32_t)(((aRowL + mt * 16) * SAS + aColL + kk) * 2);
                ldsm4(afr[mt], sAh_b + off);
            }
#pragma unroll
            for (int ntp = 0; ntp < 2; ntp++) {
                uint32_t off;
                if (!TRANS_B)
                    off = (uint32_t)(((bRowL + kk) * SBS + bColL + ntp * 16) * 2);
                else
                    off = (uint32_t)(((bRowL + ntp * 16) * SBS + bColL + kk) * 2);
                if (!TRANS_B) {
                    ldsm4t(&bh[ntp * 4], sBh_b + off);
                    ldsm4t(&bl[ntp * 4], sBl_b + off);
                } else {
                    ldsm4(&bh[ntp * 4], sBh_b + off);
                    ldsm4(&bl[ntp * 4], sBl_b + off);
                }
            }
#pragma unroll
            for (int mt = 0; mt < 2; mt++)
#pragma unroll
                for (int nt = 0; nt < 4; nt++) {
                    const uint32_t* bp = &bh[(nt >> 1) * 4 + (nt & 1) * 2];
                    const uint32_t* lp = &bl[(nt >> 1) * 4 + (nt & 1) * 2];
                    mma_bf16(acc[mt][nt], afr[mt], bp);
                    mma_bf16(acc[mt][nt], afr[mt], lp);
                }
#pragma unroll
            for (int mt = 0; mt < 2; mt++) {
                uint32_t off = (uint32_t)(((aRowL + mt * 16) * SAS + aColL + kk) * 2);
                ldsm4(afr[mt], sAl_b + off);
            }
#pragma unroll
            for (int mt = 0; mt < 2; mt++)
#pragma unroll
                for (int nt = 0; nt < 4; nt++)
                    mma_bf16(acc[mt][nt], afr[mt], &bh[(nt >> 1) * 4 + (nt & 1) * 2]);
        }

        if (c + 1 < nchunk) {
            __syncthreads();
            sts();
            __syncthreads();
        }
    }

    // ---- epilogue ----
    const int r0 = bm + wm * 32 + (lane >> 2);
    const int c0 = bn + wn * 32 + (lane & 3) * 2;
#pragma unroll
    for (int mt = 0; mt < 2; mt++)
#pragma unroll
        for (int nt = 0; nt < 4; nt++) {
            const int row = r0 + mt * 16;
            const int col = c0 + nt * 8;
            float2 v0, v1;
            v0.x = acc[mt][nt][0] * alpha; v0.y = acc[mt][nt][1] * alpha;
            v1.x = acc[mt][nt][2] * alpha; v1.y = acc[mt][nt][3] * alpha;
            if (bias) {
                v0.x += bias[col]; v0.y += bias[col + 1];
                v1.x += bias[col]; v1.y += bias[col + 1];
            }
            *reinterpret_cast<float2*>(C + (size_t)row * ldc + col) = v0;
            *reinterpret_cast<float2*>(C + (size_t)(row + 8) * ldc + col) = v1;
        }
}

// ---------------- K1: projections qp = query@Wq, kp = key@Wk, vp = value@Wq ----------------
__global__ void __launch_bounds__(256) k_proj(
    const float* __restrict__ q, const float* __restrict__ k,
    const float* __restrict__ v,
    const float* __restrict__ Wq, const float* __restrict__ Wk)
{
    int z = blockIdx.z;
    const float* A = (z == 0) ? q : (z == 1) ? k : v;
    const float* W = (z == 1) ? Wk : Wq;   // value uses Wq (bug preserved from source)
    float* C = (z == 0) ? g_qp : (z == 1) ? g_kp : g_vp;
    gemm_mma<false>(A, NE, W, NE, C, NE, NE, 1.0f, nullptr);
}

// ---------------- K2 (merged): wk2 (z<8), S1 (z in 8..23) ----------------
__global__ void __launch_bounds__(256) k_mid(const float* __restrict__ Wr)
{
    const int z = blockIdx.z;
    if (z < 8) {
        // Wk2[b,k,h,:] = (1/8) * kp_head(b,k,h,:) @ Wr[h*64:(h+1)*64, :]
        const int h = z;
        gemm_mma<false>(g_kp + h * ND, NE,
                        Wr + (size_t)h * ND * NE, NE,
                        g_wk2 + (size_t)h * NE, NH * NE,
                        ND, 0.125f, nullptr);
    } else {
        // S1[b,h,q,k] = (1/8) * qp_h @ kp_h^T
        if (blockIdx.x >= 4 || blockIdx.y >= 2) return;
        const int zz = z - 8;            // b*NH + h
        const int b = zz >> 3, h = zz & 7;
        gemm_mma<true>(g_qp + (size_t)b * NL * NE + h * ND, NE,
                       g_kp + (size_t)b * NL * NE + h * ND, NE,
                       g_S1 + (size_t)zz * NL * NL, NL,
                       ND, 0.125f, nullptr);
    }
}

// ---------------- K3: bias2[b,k,h] = (1/8) * dot(br_head, kp_head) ----------------
__global__ void k_bias2(const float* __restrict__ br)
{
    int idx = blockIdx.x * blockDim.x + threadIdx.x;  // NB*NL*NH = 4096
    if (idx >= NB * NL * NH) return;
    int h = idx & (NH - 1);
    int row = idx >> 3;
    float s = 0.f;
#pragma unroll 8
    for (int e = 0; e < ND; e++)
        s += br[h * ND + e] * g_kp[(size_t)row * NE + h * ND + e];
    g_bias2[idx] = s * 0.125f;
}

// ---------------- K4: relation stream v5 — rolling ring, 2 blocks/SM ----------------
// Block = (kpos, b, qquarter): 64 q-rows, 256 threads = 8 warps.
// Warp w owns rows {o*32 + w*4 .. +3} for o in {0,1}; 8 chunks/warp
// (chunk c: row group o = c>>2, g-stage s = c&3; 4 rows x 128 g = 2KB).
// Depth-5 per-warp ring, one commit group per chunk, empty commits pad the
// accounting. No block syncs in the loop.
// smem: wk2 16KB @0, bias2 @16384, ring @16416: [8 warps][5][2048B] = 96KB.
// Total 98336 B -> with __launch_bounds__(256,2): 2 blocks/SM, so one block's
// prologue/epilogue hides under the other's mainloop.
#define REL_D 5
#define REL_SMEM (16416 + 8 * REL_D * 2048)
__global__ void __launch_bounds__(256, 2) k_rel(const float* __restrict__ relation)
{
    extern __shared__ char dsm[];
    float* wk  = reinterpret_cast<float*>(dsm);           // [8][512]
    float* b2s = reinterpret_cast<float*>(dsm + 16384);   // [8]
    char* ring = dsm + 16416;                             // [8][REL_D][2048]

    const int kpos = blockIdx.x;
    const int b = blockIdx.y;
    const int qbase = blockIdx.z * 64;
    const int tid = threadIdx.x;
    const int warp = tid >> 5;     // 0..7
    const int lane = tid & 31;

    const uint32_t wbase = smem_addr_u32(ring) + warp * (REL_D * 2048);
    const float* relw = relation +
        ((size_t)(b * NL + qbase + warp * 4) * NL + kpos) * NE + lane * 4;

    auto issue_chunk = [&](int c) {
        const int o = c >> 2, s = c & 3;
        const int slot = c % REL_D;
        const uint32_t dst = wbase + slot * 2048 + lane * 16;
        const float* src = relw + (size_t)(o * 32) * (NL * NE) + s * 128;
#pragma unroll
        for (int j = 0; j < 4; j++)
            CP_ASYNC_CG(dst + j * 512, src + (size_t)j * (NL * NE));
        CP_ASYNC_COMMIT();
    };

    // prologue: fill the ring
#pragma unroll
    for (int c = 0; c < REL_D; c++) issue_chunk(c);

    // cooperative wk2 + bias2 load (overlaps cp.async fetch)
    {
        const float4* src = reinterpret_cast<const float4*>(
            g_wk2 + (size_t)(b * NL + kpos) * NH * NE);
        float4* dst4 = reinterpret_cast<float4*>(wk);
        for (int i = tid; i < NH * NE / 4; i += 256) dst4[i] = src[i];
        if (tid < NH) b2s[tid] = g_bias2[(size_t)(b * NL + kpos) * NH + tid];
    }
    __syncthreads();   // wk visible to all warps

    unsigned long long acc[32];    // acc[j*8+h], (even-g, odd-g) packed
#pragma unroll
    for (int i = 0; i < 32; i++) acc[i] = 0ull;

#pragma unroll
    for (int c = 0; c < 8; c++) {
        CP_ASYNC_WAIT(REL_D - 1);   // invariant: issued = c + REL_D -> chunk c done
        __syncwarp();

        const int o = c >> 2, s = c & 3;
        const float* stf = reinterpret_cast<const float*>(
            ring + warp * (REL_D * 2048) + (c % REL_D) * 2048);
        ulonglong2 r[4];
#pragma unroll
        for (int j = 0; j < 4; j++)
            r[j] = *reinterpret_cast<const ulonglong2*>(stf + j * 128 + lane * 4);

        const int gofs = s * 128 + lane * 4;
#pragma unroll
        for (int h = 0; h < 8; h++) {
            ulonglong2 w = *reinterpret_cast<const ulonglong2*>(&wk[h * NE + gofs]);
#pragma unroll
            for (int j = 0; j < 4; j++) {
                fma2(acc[j * 8 + h], r[j].x, w.x);
                fma2(acc[j * 8 + h], r[j].y, w.y);
            }
        }

        // keep the group accounting rolling (real chunk or empty commit)
        if (c + REL_D < 8) issue_chunk(c + REL_D);
        else CP_ASYNC_COMMIT();

        if ((c & 3) == 3) {
            // u64 butterfly transpose-reduce for row group o, then store
#pragma unroll
            for (int off = 16; off > 0; off >>= 1) {
                bool hi = (lane & off) != 0;
#pragma unroll
                for (int i = 0; i < 16; i++) {
                    if (i < off) {
                        unsigned long long send = hi ? acc[i] : acc[i + off];
                        unsigned long long recv = __shfl_xor_sync(0xffffffffu, send, off);
                        unsigned long long keep = hi ? acc[i + off] : acc[i];
                        acc[i] = add2(keep, recv);
                    }
                }
            }
            float lo, hf;
            f2unpack(lo, hf, acc[0]);
            float fin = lo + hf;
            const int j = lane >> 3;
            const int h = lane & 7;
            const int q = qbase + o * 32 + warp * 4 + j;
            g_S[(((size_t)b * NL + q) * NL + kpos) * NH + h] = fin + b2s[h];
#pragma unroll
            for (int i = 0; i < 32; i++) acc[i] = 0ull;
        }
    }
}

// ---------------- K5: softmax over k (adds S1 here, coalesced) + write probs ----------------
__global__ void __launch_bounds__(256) k_softmax(float* __restrict__ a_out, int write_a)
{
    const int q = blockIdx.x;
    const int b = blockIdx.y;
    const int tid = threadIdx.x;
    const int warp = tid >> 5;   // = head
    const int lane = tid & 31;

    __shared__ float Ss[NL][NH + 1];   // padded

    const float* Srow = g_S + (size_t)(b * NL + q) * NL * NH;
    for (int i = tid; i < NL * NH / 4; i += 256) {
        float4 v = reinterpret_cast<const float4*>(Srow)[i];
        int idx = i * 4;
        int kk = idx >> 3, h0 = idx & 7;
        Ss[kk][h0] = v.x; Ss[kk][h0 + 1] = v.y;
        Ss[kk][h0 + 2] = v.z; Ss[kk][h0 + 3] = v.w;
    }
    __syncthreads();

    const int h = warp;
    // S1[b,h,q,:] contiguous in k -> coalesced within the warp
    const float* S1h = g_S1 + (((size_t)b * NH + h) * NL + q) * NL;
    float x[8];
#pragma unroll
    for (int i = 0; i < 8; i++) x[i] = Ss[lane + 32 * i][h] + S1h[lane + 32 * i];

    float m = x[0];
#pragma unroll
    for (int i = 1; i < 8; i++) m = fmaxf(m, x[i]);
#pragma unroll
    for (int off = 16; off > 0; off >>= 1)
        m = fmaxf(m, __shfl_xor_sync(0xffffffffu, m, off));

    float e[8], s = 0.f;
#pragma unroll
    for (int i = 0; i < 8; i++) { e[i] = __expf(x[i] - m); s += e[i]; }
#pragma unroll
    for (int off = 16; off > 0; off >>= 1)
        s += __shfl_xor_sync(0xffffffffu, s, off);
    float inv = 1.0f / s;

    float* Prow = g_P + (((size_t)b * NH + h) * NL + q) * NL;
#pragma unroll
    for (int i = 0; i < 8; i++) {
        float p = e[i] * inv;
        Prow[lane + 32 * i] = p;
        Ss[lane + 32 * i][h] = p;    // own column only
    }
    __syncthreads();

    if (write_a) {
        float* arow = a_out + (size_t)(b * NL + q) * NL * NH;
        int t = tid;
        float4 v0 = make_float4(Ss[t][0], Ss[t][1], Ss[t][2], Ss[t][3]);
        float4 v1 = make_float4(Ss[t][4], Ss[t][5], Ss[t][6], Ss[t][7]);
        reinterpret_cast<float4*>(arow + t * 8)[0] = v0;
        reinterpret_cast<float4*>(arow + t * 8)[1] = v1;
    }
}

// ---------------- K6: attn = P @ vp per (b,h) ----------------
__global__ void __launch_bounds__(256) k_attn()
{
    int z = blockIdx.z;           // b*NH + h
    int b = z >> 3, h = z & 7;
    const float* A = g_P + (size_t)z * NL * NL;              // L x L
    const float* Bw = g_vp + (size_t)b * NL * NE + h * ND;   // L x 64, ldb=NE
    float* C = g_attn + (size_t)b * NL * NE + h * ND;        // ldc=NE
    gemm_mma<false>(A, NL, Bw, NE, C, NE, NL, 1.0f, nullptr);
}

// ---------------- K7: out = attn @ Wo^T + bo ----------------
__global__ void __launch_bounds__(256) k_out(
    const float* __restrict__ Wo, const float* __restrict__ bo,
    float* __restrict__ out)
{
    gemm_mma<true>(g_attn, NE, Wo, NE, out, NE, NE, 1.0f, bo);
}

// ---------------- launch ----------------
extern "C" void kernel_launch(void* const* d_in, const int* in_sizes, int n_in,
                              void* d_out, int out_size)
{
    const float* query    = (const float*)d_in[0];
    const float* key      = (const float*)d_in[1];
    const float* value    = (const float*)d_in[2];
    const float* relation = (const float*)d_in[3];
    const float* Wq       = (const float*)d_in[4];
    const float* Wk       = (const float*)d_in[5];
    // d_in[6] = Wv — unused (source bug: value projected with Wq)
    const float* Wr       = (const float*)d_in[7];
    const float* br       = (const float*)d_in[8];
    const float* Wo       = (const float*)d_in[9];
    const float* bo       = (const float*)d_in[10];

    float* out = (float*)d_out;
    const int out_elems = NB * NL * NE;            // 262144
    const int a_elems   = NB * NL * NL * NH;       // 1048576
    int write_a = (out_size >= out_elems + a_elems) ? 1 : 0;
    float* a_out = out + out_elems;

    // raise dynamic-smem limit for k_rel (capture-safe: not a stream op)
    cudaFuncSetAttribute((const void*)k_rel,
                         cudaFuncAttributeMaxDynamicSharedMemorySize, REL_SMEM);

    dim3 blk(256);
    k_proj   <<<dim3(8, 4, 3),   blk>>>(query, key, value, Wq, Wk);
    k_mid    <<<dim3(8, 4, 24),  blk>>>(Wr);
    k_bias2  <<<16, 256>>>(br);
    k_rel    <<<dim3(NL, NB, 4), dim3(256), REL_SMEM>>>(relation);  // idx 3 -> profiled
    k_softmax<<<dim3(NL, NB),    blk>>>(a_out, write_a);
    k_attn   <<<dim3(1, 2, 16),  blk>>>();
    k_out    <<<dim3(8, 4, 1),   blk>>>(Wo, bo, out);
}

// round 17
// speedup vs baseline: 1.2101x; 1.0601x over previous
#include <cuda_runtime.h>
#include <cuda_bf16.h>
#include <cstdint>

// Problem constants
#define NB 2
#define NL 256
#define NE 512
#define NH 8
#define ND 64   // head dim
// scale = 1/sqrt(64) = 0.125

// ---------------- device scratch (no allocations allowed) ----------------
__device__ float g_qp[NB*NL*NE];
__device__ float g_kp[NB*NL*NE];
__device__ float g_vp[NB*NL*NE];
__device__ float g_wk2[NB*NL*NH*NE];     // [b,k,h,g], pre-scaled by 1/8
__device__ float g_bias2[NB*NL*NH];      // pre-scaled by 1/8
__device__ float g_S1[NB*NH*NL*NL];      // [b,h,q,k], pre-scaled by 1/8
__device__ float g_S[NB*NL*NL*NH];       // rel logit part, [b,q,k,h]
__device__ float g_P[NB*NH*NL*NL];       // probs, [b,h,q,k]
__device__ float g_attn[NB*NL*NE];       // [b,q, h*64+e]

// ---------------- cp.async helpers (base PTX, sm_80+) ----------------
#define CP_ASYNC_CG(dst_u32, src_ptr) \
    asm volatile("cp.async.cg.shared.global [%0], [%1], 16;" \
        :: "r"(dst_u32), "l"(src_ptr) : "memory")
#define CP_ASYNC_COMMIT() \
    asm volatile("cp.async.commit_group;" ::: "memory")
#define CP_ASYNC_WAIT(N) \
    asm volatile("cp.async.wait_group %0;" :: "n"(N) : "memory")

// ---------------- warp-mma helpers (base PTX, sm_80+: valid on sm_103) ----------------
__device__ __forceinline__ uint32_t smem_addr_u32(const void* p) {
    return (uint32_t)__cvta_generic_to_shared(p);
}
__device__ __forceinline__ void ldsm4(uint32_t* r, uint32_t a) {
    asm volatile("ldmatrix.sync.aligned.m8n8.x4.shared.b16 {%0,%1,%2,%3}, [%4];"
        : "=r"(r[0]), "=r"(r[1]), "=r"(r[2]), "=r"(r[3]) : "r"(a));
}
__device__ __forceinline__ void ldsm4t(uint32_t* r, uint32_t a) {
    asm volatile("ldmatrix.sync.aligned.m8n8.x4.trans.shared.b16 {%0,%1,%2,%3}, [%4];"
        : "=r"(r[0]), "=r"(r[1]), "=r"(r[2]), "=r"(r[3]) : "r"(a));
}
__device__ __forceinline__ void mma_bf16(float* c, const uint32_t* a, const uint32_t* b) {
    asm volatile("mma.sync.aligned.m16n8k16.row.col.f32.bf16.bf16.f32 "
        "{%0,%1,%2,%3}, {%4,%5,%6,%7}, {%8,%9}, {%0,%1,%2,%3};"
        : "+f"(c[0]), "+f"(c[1]), "+f"(c[2]), "+f"(c[3])
        : "r"(a[0]), "r"(a[1]), "r"(a[2]), "r"(a[3]), "r"(b[0]), "r"(b[1]));
}

// ---------------- GEMM v5c: bf16-split tensor-core GEMM, double-buffered ----------------
// C[m,n] = alpha * sum_k A[m,k]*B[k,n]   (TRANS_B: B stored [n,k])  (+bias[n])
// Block tile 128(m) x 64(n), 256 threads = 8 warps (4m x 2n), warp tile 32x32.
// Per 32-wide K-chunk: stage A,B split into bf16 hi/lo smem tiles (2-deep
// double buffer, ONE syncthreads per chunk), MMA passes Ah*Bh + Ah*Bl + Al*Bh.
template<bool TRANS_B>
__device__ __forceinline__ void gemm_mma(
    const float* __restrict__ A, int lda,
    const float* __restrict__ B, int ldb,
    float* __restrict__ C, int ldc,
    int K, float alpha, const float* __restrict__ bias)
{
    constexpr int SAS = 40;                  // sA row stride (elems): 80B, 16B-aligned
    constexpr int SBR = TRANS_B ? 64 : 32;   // sB rows
    constexpr int SBS = TRANS_B ? 40 : 72;   // sB row stride (80B / 144B)
    constexpr int ABYTES = 128 * SAS * 2;
    constexpr int BBYTES = SBR * SBS * 2;
    __shared__ __nv_bfloat16 sAh[2][128 * SAS], sAl[2][128 * SAS];
    __shared__ __nv_bfloat16 sBh[2][SBR * SBS], sBl[2][SBR * SBS];

    const int tid = threadIdx.x;
    const int lane = tid & 31;
    const int wid = tid >> 5;
    const int wm = wid & 3;                  // warp m index (0..3)
    const int wn = wid >> 2;                 // warp n index (0..1)
    const int bm = blockIdx.y * 128;
    const int bn = blockIdx.x * 64;

    const uint32_t sAh_b = smem_addr_u32(sAh);
    const uint32_t sAl_b = smem_addr_u32(sAl);
    const uint32_t sBh_b = smem_addr_u32(sBh);
    const uint32_t sBl_b = smem_addr_u32(sBl);

    const int aRowL = wm * 32 + (lane & 15);          // + mt*16
    const int aColL = (lane >> 4) * 8;                // + kk
    const int bRowL = TRANS_B ? (wn * 32 + (lane & 7) + (lane >> 4) * 8)
                              : ((lane & 7) + ((lane >> 3) & 1) * 8);
    const int bColL = TRANS_B ? (((lane >> 3) & 1) * 8)
                              : (wn * 32 + (lane >> 4) * 8);

    // staging indices
    const int aSRow = tid >> 3, aSC4 = (tid & 7) * 4;
    const int bSRowN = tid >> 4, bSC4N = (tid & 15) * 4;
    const int bSRowT = tid >> 3, bSC4T = (tid & 7) * 4;

    float4 aR[4], bR[2];
    auto ldg = [&](int k0) {
#pragma unroll
        for (int i = 0; i < 4; i++)
            aR[i] = *reinterpret_cast<const float4*>(
                A + (size_t)(bm + aSRow + i * 32) * lda + k0 + aSC4);
#pragma unroll
        for (int i = 0; i < 2; i++) {
            if (!TRANS_B)
                bR[i] = *reinterpret_cast<const float4*>(
                    B + (size_t)(k0 + bSRowN + i * 16) * ldb + bn + bSC4N);
            else
                bR[i] = *reinterpret_cast<const float4*>(
                    B + (size_t)(bn + bSRowT + i * 32) * ldb + k0 + bSC4T);
        }
    };
    auto split_store = [&](__nv_bfloat16* hB, __nv_bfloat16* lB, int idx, float4 v) {
        __nv_bfloat162 h01 = __floats2bfloat162_rn(v.x, v.y);
        __nv_bfloat162 h23 = __floats2bfloat162_rn(v.z, v.w);
        float2 f01 = __bfloat1622float2(h01);
        float2 f23 = __bfloat1622float2(h23);
        __nv_bfloat162 l01 = __floats2bfloat162_rn(v.x - f01.x, v.y - f01.y);
        __nv_bfloat162 l23 = __floats2bfloat162_rn(v.z - f23.x, v.w - f23.y);
        *reinterpret_cast<__nv_bfloat162*>(&hB[idx])     = h01;
        *reinterpret_cast<__nv_bfloat162*>(&hB[idx + 2]) = h23;
        *reinterpret_cast<__nv_bfloat162*>(&lB[idx])     = l01;
        *reinterpret_cast<__nv_bfloat162*>(&lB[idx + 2]) = l23;
    };
    auto sts = [&](int p) {
#pragma unroll
        for (int i = 0; i < 4; i++)
            split_store(sAh[p], sAl[p], (aSRow + i * 32) * SAS + aSC4, aR[i]);
#pragma unroll
        for (int i = 0; i < 2; i++) {
            int idx = (!TRANS_B) ? ((bSRowN + i * 16) * SBS + bSC4N)
                                 : ((bSRowT + i * 32) * SBS + bSC4T);
            split_store(sBh[p], sBl[p], idx, bR[i]);
        }
    };

    float acc[2][4][4];
#pragma unroll
    for (int mt = 0; mt < 2; mt++)
#pragma unroll
        for (int nt = 0; nt < 4; nt++)
#pragma unroll
            for (int j = 0; j < 4; j++) acc[mt][nt][j] = 0.f;

    const int nchunk = K / 32;
    ldg(0);
    sts(0);
    __syncthreads();

    int p = 0;
    for (int c = 0; c < nchunk; ++c) {
        if (c + 1 < nchunk) ldg((c + 1) * 32);   // prefetch overlaps MMAs below
        const uint32_t aOfs = (uint32_t)(p * ABYTES);
        const uint32_t bOfs = (uint32_t)(p * BBYTES);

#pragma unroll
        for (int kk = 0; kk < 32; kk += 16) {
            uint32_t afr[2][4], bh[8], bl[8];
#pragma unroll
            for (int mt = 0; mt < 2; mt++) {
                uint32_t off = (uint32_t)(((aRowL + mt * 16) * SAS + aColL + kk) * 2);
                ldsm4(afr[mt], sAh_b + aOfs + off);
            }
#pragma unroll
            for (int ntp = 0; ntp < 2; ntp++) {
                uint32_t off;
                if (!TRANS_B)
                    off = (uint32_t)(((bRowL + kk) * SBS + bColL + ntp * 16) * 2);
                else
                    off = (uint32_t)(((bRowL + ntp * 16) * SBS + bColL + kk) * 2);
                if (!TRANS_B) {
                    ldsm4t(&bh[ntp * 4], sBh_b + bOfs + off);
                    ldsm4t(&bl[ntp * 4], sBl_b + bOfs + off);
                } else {
                    ldsm4(&bh[ntp * 4], sBh_b + bOfs + off);
                    ldsm4(&bl[ntp * 4], sBl_b + bOfs + off);
                }
            }
#pragma unroll
            for (int mt = 0; mt < 2; mt++)
#pragma unroll
                for (int nt = 0; nt < 4; nt++) {
                    const uint32_t* bp = &bh[(nt >> 1) * 4 + (nt & 1) * 2];
                    const uint32_t* lp = &bl[(nt >> 1) * 4 + (nt & 1) * 2];
                    mma_bf16(acc[mt][nt], afr[mt], bp);
                    mma_bf16(acc[mt][nt], afr[mt], lp);
                }
#pragma unroll
            for (int mt = 0; mt < 2; mt++) {
                uint32_t off = (uint32_t)(((aRowL + mt * 16) * SAS + aColL + kk) * 2);
                ldsm4(afr[mt], sAl_b + aOfs + off);
            }
#pragma unroll
            for (int mt = 0; mt < 2; mt++)
#pragma unroll
                for (int nt = 0; nt < 4; nt++)
                    mma_bf16(acc[mt][nt], afr[mt], &bh[(nt >> 1) * 4 + (nt & 1) * 2]);
        }

        if (c + 1 < nchunk) {
            sts(p ^ 1);          // other buffer: safe, all reads of it finished
            __syncthreads();     // one barrier per chunk
            p ^= 1;
        }
    }

    // ---- epilogue ----
    const int r0 = bm + wm * 32 + (lane >> 2);
    const int c0 = bn + wn * 32 + (lane & 3) * 2;
#pragma unroll
    for (int mt = 0; mt < 2; mt++)
#pragma unroll
        for (int nt = 0; nt < 4; nt++) {
            const int row = r0 + mt * 16;
            const int col = c0 + nt * 8;
            float2 v0, v1;
            v0.x = acc[mt][nt][0] * alpha; v0.y = acc[mt][nt][1] * alpha;
            v1.x = acc[mt][nt][2] * alpha; v1.y = acc[mt][nt][3] * alpha;
            if (bias) {
                v0.x += bias[col]; v0.y += bias[col + 1];
                v1.x += bias[col]; v1.y += bias[col + 1];
            }
            *reinterpret_cast<float2*>(C + (size_t)row * ldc + col) = v0;
            *reinterpret_cast<float2*>(C + (size_t)(row + 8) * ldc + col) = v1;
        }
}

// ---------------- K1: projections qp = query@Wq, kp = key@Wk, vp = value@Wq ----------------
__global__ void __launch_bounds__(256) k_proj(
    const float* __restrict__ q, const float* __restrict__ k,
    const float* __restrict__ v,
    const float* __restrict__ Wq, const float* __restrict__ Wk)
{
    int z = blockIdx.z;
    const float* A = (z == 0) ? q : (z == 1) ? k : v;
    const float* W = (z == 1) ? Wk : Wq;   // value uses Wq (bug preserved from source)
    float* C = (z == 0) ? g_qp : (z == 1) ? g_kp : g_vp;
    gemm_mma<false>(A, NE, W, NE, C, NE, NE, 1.0f, nullptr);
}

// ---------------- K2 (merged): wk2 (z<8), S1 (z in 8..23) ----------------
__global__ void __launch_bounds__(256) k_mid(const float* __restrict__ Wr)
{
    const int z = blockIdx.z;
    if (z < 8) {
        // Wk2[b,k,h,:] = (1/8) * kp_head(b,k,h,:) @ Wr[h*64:(h+1)*64, :]
        const int h = z;
        gemm_mma<false>(g_kp + h * ND, NE,
                        Wr + (size_t)h * ND * NE, NE,
                        g_wk2 + (size_t)h * NE, NH * NE,
                        ND, 0.125f, nullptr);
    } else {
        // S1[b,h,q,k] = (1/8) * qp_h @ kp_h^T
        if (blockIdx.x >= 4 || blockIdx.y >= 2) return;
        const int zz = z - 8;            // b*NH + h
        const int b = zz >> 3, h = zz & 7;
        gemm_mma<true>(g_qp + (size_t)b * NL * NE + h * ND, NE,
                       g_kp + (size_t)b * NL * NE + h * ND, NE,
                       g_S1 + (size_t)zz * NL * NL, NL,
                       ND, 0.125f, nullptr);
    }
}

// ---------------- K3: bias2[b,k,h] = (1/8) * dot(br_head, kp_head) ----------------
__global__ void k_bias2(const float* __restrict__ br)
{
    int idx = blockIdx.x * blockDim.x + threadIdx.x;  // NB*NL*NH = 4096
    if (idx >= NB * NL * NH) return;
    int h = idx & (NH - 1);
    int row = idx >> 3;
    float s = 0.f;
#pragma unroll 8
    for (int e = 0; e < ND; e++)
        s += br[h * ND + e] * g_kp[(size_t)row * NE + h * ND + e];
    g_bias2[idx] = s * 0.125f;
}

// ---------------- K4: relation stream v6 — rolling ring, 3 blocks/SM ----------------
// Block = (kpos, b, qquarter): 64 q-rows, 256 threads = 8 warps.
// Warp w owns rows {o*32 + w*4 .. +3} for o in {0,1}; 8 chunks/warp
// (chunk c: row group o = c>>2, g-stage s = c&3; 4 rows x 128 g = 2KB).
// Depth-3 per-warp ring; refill issued right after the chunk's data is read
// into registers (safe: each lane re-writes exactly the bytes it just read).
// Scalar fp32 accumulators (32 regs) so launch_bounds(256,3) fits w/o spills.
// smem: wk2 16KB @0, bias2 @16384, ring @16416: [8][3][2048B] = 48KB.
// Total 65568 B -> 3 blocks/SM = 24 warps/SM.
#define REL_D 3
#define REL_SMEM (16416 + 8 * REL_D * 2048)
__global__ void __launch_bounds__(256, 3) k_rel(const float* __restrict__ relation)
{
    extern __shared__ char dsm[];
    float* wk  = reinterpret_cast<float*>(dsm);           // [8][512]
    float* b2s = reinterpret_cast<float*>(dsm + 16384);   // [8]
    char* ring = dsm + 16416;                             // [8][REL_D][2048]

    const int kpos = blockIdx.x;
    const int b = blockIdx.y;
    const int qbase = blockIdx.z * 64;
    const int tid = threadIdx.x;
    const int warp = tid >> 5;     // 0..7
    const int lane = tid & 31;

    const uint32_t wbase = smem_addr_u32(ring) + warp * (REL_D * 2048);
    const float* relw = relation +
        ((size_t)(b * NL + qbase + warp * 4) * NL + kpos) * NE + lane * 4;

    auto issue_chunk = [&](int c) {
        const int o = c >> 2, s = c & 3;
        const int slot = c % REL_D;
        const uint32_t dst = wbase + slot * 2048 + lane * 16;
        const float* src = relw + (size_t)(o * 32) * (NL * NE) + s * 128;
#pragma unroll
        for (int j = 0; j < 4; j++)
            CP_ASYNC_CG(dst + j * 512, src + (size_t)j * (NL * NE));
        CP_ASYNC_COMMIT();
    };

    // prologue: fill the ring
#pragma unroll
    for (int c = 0; c < REL_D; c++) issue_chunk(c);

    // cooperative wk2 + bias2 load (overlaps cp.async fetch)
    {
        const float4* src = reinterpret_cast<const float4*>(
            g_wk2 + (size_t)(b * NL + kpos) * NH * NE);
        float4* dst4 = reinterpret_cast<float4*>(wk);
        for (int i = tid; i < NH * NE / 4; i += 256) dst4[i] = src[i];
        if (tid < NH) b2s[tid] = g_bias2[(size_t)(b * NL + kpos) * NH + tid];
    }
    __syncthreads();   // wk visible to all warps

    float acc[32];    // acc[j*8+h], scalar fp32
#pragma unroll
    for (int i = 0; i < 32; i++) acc[i] = 0.f;

#pragma unroll
    for (int c = 0; c < 8; c++) {
        CP_ASYNC_WAIT(REL_D - 1);   // invariant: issued = c + REL_D -> chunk c done
        __syncwarp();

        const int o = c >> 2, s = c & 3;
        const float* stf = reinterpret_cast<const float*>(
            ring + warp * (REL_D * 2048) + (c % REL_D) * 2048);
        float4 r[4];
#pragma unroll
        for (int j = 0; j < 4; j++)
            r[j] = *reinterpret_cast<const float4*>(stf + j * 128 + lane * 4);

        // refill the slot we just consumed (issue hides under the FMAs below)
        if (c + REL_D < 8) issue_chunk(c + REL_D);
        else CP_ASYNC_COMMIT();

        const int gofs = s * 128 + lane * 4;
#pragma unroll
        for (int h = 0; h < 8; h++) {
            float4 w = *reinterpret_cast<const float4*>(&wk[h * NE + gofs]);
#pragma unroll
            for (int j = 0; j < 4; j++)
                acc[j * 8 + h] += r[j].x * w.x + r[j].y * w.y
                                + r[j].z * w.z + r[j].w * w.w;
        }

        if ((c & 3) == 3) {
            // float butterfly transpose-reduce: lane l ends with sum of acc[l]
#pragma unroll
            for (int off = 16; off > 0; off >>= 1) {
                bool hi = (lane & off) != 0;
#pragma unroll
                for (int i = 0; i < 16; i++) {
                    if (i < off) {
                        float send = hi ? acc[i] : acc[i + off];
                        float recv = __shfl_xor_sync(0xffffffffu, send, off);
                        acc[i] = (hi ? acc[i + off] : acc[i]) + recv;
                    }
                }
            }
            const int j = lane >> 3;
            const int h = lane & 7;
            const int q = qbase + o * 32 + warp * 4 + j;
            g_S[(((size_t)b * NL + q) * NL + kpos) * NH + h] = acc[0] + b2s[h];
#pragma unroll
            for (int i = 0; i < 32; i++) acc[i] = 0.f;
        }
    }
}

// ---------------- K5: softmax over k (adds S1 here, coalesced) + write probs ----------------
__global__ void __launch_bounds__(256) k_softmax(float* __restrict__ a_out, int write_a)
{
    const int q = blockIdx.x;
    const int b = blockIdx.y;
    const int tid = threadIdx.x;
    const int warp = tid >> 5;   // = head
    const int lane = tid & 31;

    __shared__ float Ss[NL][NH + 1];   // padded

    const float* Srow = g_S + (size_t)(b * NL + q) * NL * NH;
    for (int i = tid; i < NL * NH / 4; i += 256) {
        float4 v = reinterpret_cast<const float4*>(Srow)[i];
        int idx = i * 4;
        int kk = idx >> 3, h0 = idx & 7;
        Ss[kk][h0] = v.x; Ss[kk][h0 + 1] = v.y;
        Ss[kk][h0 + 2] = v.z; Ss[kk][h0 + 3] = v.w;
    }
    __syncthreads();

    const int h = warp;
    // S1[b,h,q,:] contiguous in k -> coalesced within the warp
    const float* S1h = g_S1 + (((size_t)b * NH + h) * NL + q) * NL;
    float x[8];
#pragma unroll
    for (int i = 0; i < 8; i++) x[i] = Ss[lane + 32 * i][h] + S1h[lane + 32 * i];

    float m = x[0];
#pragma unroll
    for (int i = 1; i < 8; i++) m = fmaxf(m, x[i]);
#pragma unroll
    for (int off = 16; off > 0; off >>= 1)
        m = fmaxf(m, __shfl_xor_sync(0xffffffffu, m, off));

    float e[8], s = 0.f;
#pragma unroll
    for (int i = 0; i < 8; i++) { e[i] = __expf(x[i] - m); s += e[i]; }
#pragma unroll
    for (int off = 16; off > 0; off >>= 1)
        s += __shfl_xor_sync(0xffffffffu, s, off);
    float inv = 1.0f / s;

    float* Prow = g_P + (((size_t)b * NH + h) * NL + q) * NL;
#pragma unroll
    for (int i = 0; i < 8; i++) {
        float p = e[i] * inv;
        Prow[lane + 32 * i] = p;
        Ss[lane + 32 * i][h] = p;    // own column only
    }
    __syncthreads();

    if (write_a) {
        float* arow = a_out + (size_t)(b * NL + q) * NL * NH;
        int t = tid;
        float4 v0 = make_float4(Ss[t][0], Ss[t][1], Ss[t][2], Ss[t][3]);
        float4 v1 = make_float4(Ss[t][4], Ss[t][5], Ss[t][6], Ss[t][7]);
        reinterpret_cast<float4*>(arow + t * 8)[0] = v0;
        reinterpret_cast<float4*>(arow + t * 8)[1] = v1;
    }
}

// ---------------- K6: attn = P @ vp per (b,h) ----------------
__global__ void __launch_bounds__(256) k_attn()
{
    int z = blockIdx.z;           // b*NH + h
    int b = z >> 3, h = z & 7;
    const float* A = g_P + (size_t)z * NL * NL;              // L x L
    const float* Bw = g_vp + (size_t)b * NL * NE + h * ND;   // L x 64, ldb=NE
    float* C = g_attn + (size_t)b * NL * NE + h * ND;        // ldc=NE
    gemm_mma<false>(A, NL, Bw, NE, C, NE, NL, 1.0f, nullptr);
}

// ---------------- K7: out = attn @ Wo^T + bo ----------------
__global__ void __launch_bounds__(256) k_out(
    const float* __restrict__ Wo, const float* __restrict__ bo,
    float* __restrict__ out)
{
    gemm_mma<true>(g_attn, NE, Wo, NE, out, NE, NE, 1.0f, bo);
}

// ---------------- launch ----------------
extern "C" void kernel_launch(void* const* d_in, const int* in_sizes, int n_in,
                              void* d_out, int out_size)
{
    const float* query    = (const float*)d_in[0];
    const float* key      = (const float*)d_in[1];
    const float* value    = (const float*)d_in[2];
    const float* relation = (const float*)d_in[3];
    const float* Wq       = (const float*)d_in[4];
    const float* Wk       = (const float*)d_in[5];
    // d_in[6] = Wv — unused (source bug: value projected with Wq)
    const float* Wr       = (const float*)d_in[7];
    const float* br       = (const float*)d_in[8];
    const float* Wo       = (const float*)d_in[9];
    const float* bo       = (const float*)d_in[10];

    float* out = (float*)d_out;
    const int out_elems = NB * NL * NE;            // 262144
    const int a_elems   = NB * NL * NL * NH;       // 1048576
    int write_a = (out_size >= out_elems + a_elems) ? 1 : 0;
    float* a_out = out + out_elems;

    // raise dynamic-smem limit for k_rel (capture-safe: not a stream op)
    cudaFuncSetAttribute((const void*)k_rel,
                         cudaFuncAttributeMaxDynamicSharedMemorySize, REL_SMEM);

    dim3 blk(256);
    k_proj   <<<dim3(8, 4, 3),   blk>>>(query, key, value, Wq, Wk);
    k_mid    <<<dim3(8, 4, 24),  blk>>>(Wr);
    k_bias2  <<<16, 256>>>(br);
    k_rel    <<<dim3(NL, NB, 4), dim3(256), REL_SMEM>>>(relation);  // idx 3 -> profiled
    k_softmax<<<dim3(NL, NB),    blk>>>(a_out, write_a);
    k_attn   <<<dim3(1, 2, 16),  blk>>>();
    k_out    <<<dim3(8, 4, 1),   blk>>>(Wo, bo, out);
}